// round 11
// baseline (speedup 1.0000x reference)
#include <cuda_runtime.h>
#include <cuda_bf16.h>
#include <math.h>

#define N_ANCH   102400
#define FMP      320
#define NCLS     80
#define TOPK     1000
#define CAP      4096
#define NBINS    65536
#define NPART    64
#define NBLK     148
#define NWARPS   (NBLK * 32)     // 4736 warps grid-wide
#define STAGE    192             // rows staged in shared for NMS

// libdevice precise expf — the exact function XLA:GPU links for HLO exp(f32).
extern "C" __device__ float __nv_expf(float);

// ------- state that must be zero at the start of every replay (ONE memset) --
struct GState {
    unsigned int hist[NBINS];
    unsigned int part[NPART];
    unsigned int bars[8];
    unsigned int nzmask[32];     // 1000-bit bitmap of rows with nonzero mask
    int          count;
    int          nnz;
};
__device__ GState g;

// ------- scratch fully written-before-read each replay -----------------------
__device__ __align__(16) unsigned int      d_sbits[N_ANCH];
__device__ unsigned char                   d_label[N_ANCH];
__device__ unsigned long long              d_keys[CAP];
__device__ float4                          d_boxes4[TOPK];
__device__ int                             d_tlab[TOPK];
__device__ int                             d_rowslot[TOPK];
__device__ unsigned int                    d_rowdata[TOPK * 32];
__device__ int                             d_thresh;

// XLA LogisticExpander: logistic(x) = 1/(1+exp(-x)), exp->__nv_expf, div->rn.
__device__ __forceinline__ float xsig(float x) {
    return __fdiv_rn(1.0f, __fadd_rn(1.0f, __nv_expf(-x)));
}
__device__ __forceinline__ float xfused(float h, float K) {
    return __fsqrt_rn(__fmul_rn(xsig(h), K));
}

// ---------------- software grid barrier (all 148 blocks resident) -----------
__device__ __forceinline__ void gbar(int which) {
    __syncthreads();
    if (threadIdx.x == 0) {
        __threadfence();
        unsigned arrived = atomicAdd(&g.bars[which], 1u) + 1u;
        if (arrived < NBLK) {
            volatile unsigned* c = &g.bars[which];
            while (*c < NBLK) __nanosleep(32);
        }
        __threadfence();
    }
    __syncthreads();
}

// ---------------- THE kernel -------------------------------------------------
__global__ void __launch_bounds__(1024, 1)
k_mega(const float* __restrict__ hmp, const float* __restrict__ reg,
       const float* __restrict__ iou, float* __restrict__ out) {
    __shared__ unsigned spart[NPART];
    __shared__ unsigned wtot[32];
    __shared__ unsigned whi[32];
    __shared__ int      s_pstar;
    __shared__ unsigned s_above;
    __shared__ unsigned tmp[32];
    __shared__ int      sslot[TOPK];
    __shared__ unsigned sstage[STAGE * 32];
    __shared__ unsigned skeep[32];

    const int tid  = threadIdx.x;
    const int blk  = blockIdx.x;
    const int gt   = blk * 1024 + tid;
    const int lane = tid & 31;

    // ======== S0: scores + labels + histogram (grid-stride, warp/anchor) ====
    {
        int wgid = (blk << 5) + (tid >> 5);
        for (int a = wgid; a < N_ANCH; a += NWARPS) {
            const float4* row = reinterpret_cast<const float4*>(hmp) + (size_t)a * 20;

            float4 v = make_float4(0.f, 0.f, 0.f, 0.f);
            float m = __int_as_float(0xff800000);
            if (lane < 20) {
                v = row[lane];
                m = fmaxf(fmaxf(v.x, v.y), fmaxf(v.z, v.w));
            }
            #pragma unroll
            for (int off = 16; off; off >>= 1)
                m = fmaxf(m, __shfl_xor_sync(0xffffffffu, m, off));

            float K   = xsig(iou[a]);
            float thr = m - 1e-4f;

            float best = __int_as_float(0xff800000);
            int   bi   = 0x7FFFFFFF;
            if (lane < 20) {
                int b = lane * 4;
                if (v.x >= thr) { float f = xfused(v.x, K); if (f > best) { best = f; bi = b;     } }
                if (v.y >= thr) { float f = xfused(v.y, K); if (f > best) { best = f; bi = b + 1; } }
                if (v.z >= thr) { float f = xfused(v.z, K); if (f > best) { best = f; bi = b + 2; } }
                if (v.w >= thr) { float f = xfused(v.w, K); if (f > best) { best = f; bi = b + 3; } }
            }
            unsigned cm = __ballot_sync(0xffffffffu, bi != 0x7FFFFFFF);
            if (__popc(cm) == 1) {                 // common case: one candidate
                int src = __ffs(cm) - 1;
                best = __shfl_sync(0xffffffffu, best, src);
                bi   = __shfl_sync(0xffffffffu, bi,   src);
            } else {
                #pragma unroll
                for (int off = 16; off; off >>= 1) {
                    float of = __shfl_xor_sync(0xffffffffu, best, off);
                    int   oi = __shfl_xor_sync(0xffffffffu, bi,   off);
                    if (of > best || (of == best && oi < bi)) { best = of; bi = oi; }
                }
            }

            if (lane == 0) {
                unsigned bits = __float_as_uint(best);
                d_sbits[a] = bits;
                d_label[a] = (unsigned char)bi;
                atomicAdd(&g.hist[bits >> 16], 1u);
                atomicAdd(&g.part[bits >> 26], 1u);
            }
        }
    }
    gbar(0);

    // ======== S1: exact 16-bit threshold (block 0, fully parallel) ==========
    if (blk == 0) {
        if (tid < NPART) spart[tid] = g.part[tid];
        __syncthreads();
        if (tid < 32) {
            unsigned a = spart[tid], b = spart[tid + 32];
            unsigned sa = a, sb = b;
            #pragma unroll
            for (int off = 1; off < 32; off <<= 1) {
                unsigned ta = __shfl_down_sync(0xffffffffu, sa, off);
                unsigned tb = __shfl_down_sync(0xffffffffu, sb, off);
                if (tid + off < 32) { sa += ta; sb += tb; }
            }
            unsigned totb  = __shfl_sync(0xffffffffu, sb, 0);
            unsigned sufa  = sa + totb;            // inclusive suffix at p=tid
            unsigned sufb  = sb;                   // inclusive suffix at p=tid+32
            if (sufa >= TOPK && sufa - a < TOPK) { s_pstar = tid;      s_above = sufa - a; }
            if (sufb >= TOPK && sufb - b < TOPK) { s_pstar = tid + 32; s_above = sufb - b; }
        }
        __syncthreads();
        int base = s_pstar << 10;
        int w = tid >> 5;
        unsigned own = g.hist[base + tid];
        unsigned s = own;
        #pragma unroll
        for (int off = 1; off < 32; off <<= 1) {
            unsigned t = __shfl_down_sync(0xffffffffu, s, off);
            if (lane + off < 32) s += t;
        }
        if (lane == 0) wtot[w] = s;
        __syncthreads();
        if (tid < 32) {
            unsigned v = wtot[tid];
            unsigned sv = v;
            #pragma unroll
            for (int off = 1; off < 32; off <<= 1) {
                unsigned t = __shfl_down_sync(0xffffffffu, sv, off);
                if (tid + off < 32) sv += t;
            }
            whi[tid] = sv - v;                     // totals of warps above mine
        }
        __syncthreads();
        unsigned tot = s_above + whi[w] + s;       // count of scores >= this bin
        if (tot >= TOPK && tot - own < TOPK) d_thresh = base + tid;
    }
    gbar(1);

    // ======== S2: compact candidates =========================================
    {
        int th = d_thresh;
        for (int t = gt; t < N_ANCH / 4; t += NBLK * 1024) {
            uint4 s = reinterpret_cast<const uint4*>(d_sbits)[t];
            unsigned a = (unsigned)t * 4u;
            #pragma unroll
            for (int q = 0; q < 4; ++q) {
                unsigned bits = (q == 0) ? s.x : (q == 1) ? s.y : (q == 2) ? s.z : s.w;
                if ((int)(bits >> 16) >= th) {
                    int pos = atomicAdd(&g.count, 1);
                    if (pos < CAP) {
                        unsigned long long key =
                            ((unsigned long long)bits << 32) |
                            (unsigned long long)(0xFFFFFFFFu - (a + q));
                        d_keys[pos] = ~key;
                    }
                }
            }
        }
    }
    gbar(2);

    // ======== S3: rank-by-counting + decode ==================================
    {
        int M = g.count; if (M > CAP) M = CAP;
        int cand = gt >> 4;
        int sub  = gt & 15;
        if (cand < M) {
            unsigned long long key = d_keys[cand];
            int rank = 0;
            for (int k = sub; k < M; k += 16)
                rank += (d_keys[k] < key) ? 1 : 0;
            rank += __shfl_xor_sync(0xffffffffu, rank, 1);
            rank += __shfl_xor_sync(0xffffffffu, rank, 2);
            rank += __shfl_xor_sync(0xffffffffu, rank, 4);
            rank += __shfl_xor_sync(0xffffffffu, rank, 8);

            if (sub == 0 && rank < TOPK) {
                unsigned long long k0 = ~key;
                unsigned bits = (unsigned)(k0 >> 32);
                unsigned aidx = 0xFFFFFFFFu - (unsigned)(k0 & 0xFFFFFFFFull);
                float score = __uint_as_float(bits);
                int   lab   = (int)d_label[aidx];

                const float CLAMPF = 6.907755278982137f;   // log(1000)
                float4 r4 = reinterpret_cast<const float4*>(reg)[aidx];
                float e0 = __nv_expf(fminf(r4.x, CLAMPF));
                float e1 = __nv_expf(fminf(r4.y, CLAMPF));
                float e2 = __nv_expf(fminf(r4.z, CLAMPF));
                float e3 = __nv_expf(fminf(r4.w, CLAMPF));
                float ax = (float)(aidx % FMP);
                float ay = (float)(aidx / FMP);
                float b0 = fminf(1.0f, fmaxf(0.0f, __fdiv_rn(__fmul_rn(__fadd_rn(ax, -e0), 4.0f), 1280.0f)));
                float b1 = fminf(1.0f, fmaxf(0.0f, __fdiv_rn(__fmul_rn(__fadd_rn(ay, -e1), 4.0f), 1280.0f)));
                float b2 = fminf(1.0f, fmaxf(0.0f, __fdiv_rn(__fmul_rn(__fadd_rn(ax,  e2), 4.0f), 1280.0f)));
                float b3 = fminf(1.0f, fmaxf(0.0f, __fdiv_rn(__fmul_rn(__fadd_rn(ay,  e3), 4.0f), 1280.0f)));

                out[rank]        = score;
                out[TOPK + rank] = (float)lab;
                reinterpret_cast<float4*>(out + 2 * TOPK)[rank] = make_float4(b0, b1, b2, b3);
                d_boxes4[rank] = make_float4(b0, b1, b2, b3);
                d_tlab[rank]   = lab;
            }
        }
    }
    gbar(3);

    // ======== S4: suppression rows, compacted (grid-stride over i) ===========
    for (int i = blk; i < TOPK; i += NBLK) {
        int j = tid; int w = tid >> 5;
        float4 bxi = d_boxes4[i];
        float ai = __fmul_rn(__fadd_rn(bxi.z, -bxi.x), __fadd_rn(bxi.w, -bxi.y));
        int li = d_tlab[i];

        bool sup = false;
        if (j < TOPK && j > i && d_tlab[j] == li) {
            float4 bxj = d_boxes4[j];
            float aj = __fmul_rn(__fadd_rn(bxj.z, -bxj.x), __fadd_rn(bxj.w, -bxj.y));
            float wd = fmaxf(1e-10f, __fadd_rn(fminf(bxi.z, bxj.z), -fmaxf(bxi.x, bxj.x)));
            float hd = fmaxf(1e-10f, __fadd_rn(fminf(bxi.w, bxj.w), -fmaxf(bxi.y, bxj.y)));
            float inter = __fmul_rn(wd, hd);
            float den = __fadd_rn(__fadd_rn(__fadd_rn(ai, aj), -inter), 1e-10f);
            // rn32(inter/den) > 0.6f  <=>  inter/den > midpoint(0.6f, nextup(0.6f))
            sup = ((double)inter / (double)den) > 0.6000000536441802978515625;
        }
        unsigned b = __ballot_sync(0xffffffffu, sup);
        if ((j & 31) == 0) tmp[w] = b;
        __syncthreads();
        if (tid < 32) {
            unsigned x = tmp[tid];
            unsigned anyb = __ballot_sync(0xffffffffu, x != 0u);
            if (anyb) {
                int slot = 0;
                if (tid == 0) {
                    slot = atomicAdd(&g.nnz, 1);
                    d_rowslot[i] = slot;
                    atomicOr(&g.nzmask[i >> 5], 1u << (i & 31));
                }
                slot = __shfl_sync(0xffffffffu, slot, 0);
                d_rowdata[slot * 32 + tid] = x;
            }
        }
        __syncthreads();
    }
    gbar(4);

    // ======== S5: greedy NMS over compact rows (block 0) =====================
    if (blk != 0) return;
    {
        int nnz = g.nnz;
        int stagen = nnz < STAGE ? nnz : STAGE;
        for (int t = tid; t < stagen * 32; t += 1024) sstage[t] = d_rowdata[t];
        for (int t = tid; t < TOPK; t += 1024)        sslot[t]  = d_rowslot[t];
        __syncthreads();

        if (tid < 32) {
            unsigned keep = 0xFFFFFFFFu;           // lane ln: keep bits [ln*32, ln*32+31]
            unsigned nzm  = g.nzmask[lane];
            for (int wi = 0; wi < 32; ++wi) {
                unsigned bits = __shfl_sync(0xffffffffu, nzm, wi);
                while (bits) {
                    int bpos = __ffs(bits) - 1;
                    bits &= bits - 1u;
                    unsigned kw = __shfl_sync(0xffffffffu, keep, wi);
                    if ((kw >> bpos) & 1u) {
                        int i = wi * 32 + bpos;
                        int slot = sslot[i];       // shared, warp-uniform
                        unsigned roww = (slot < STAGE) ? sstage[slot * 32 + lane]
                                                       : d_rowdata[slot * 32 + lane];
                        keep &= ~roww;
                    }
                }
            }
            skeep[lane] = keep;
        }
        __syncthreads();
        if (tid < TOPK)
            out[6 * TOPK + tid] = (float)((skeep[tid >> 5] >> (tid & 31)) & 1u);
    }
}

// ---------------- launch ----------------
extern "C" void kernel_launch(void* const* d_in, const int* in_sizes, int n_in,
                              void* d_out, int out_size) {
    const float* hmp = (const float*)d_in[0];
    const float* reg = (const float*)d_in[1];
    const float* iou = (const float*)d_in[2];
    float* out = (float*)d_out;

    void* gptr = nullptr;
    cudaGetSymbolAddress(&gptr, g);
    cudaMemsetAsync(gptr, 0, sizeof(GState), 0);

    k_mega<<<NBLK, 1024>>>(hmp, reg, iou, out);
}